// round 6
// baseline (speedup 1.0000x reference)
#include <cuda_runtime.h>
#include <math.h>

#define NN 100000
#define EE 1600000
#define HH 128
#define CC 64
#define KK 10

// ---------------- device scratch (allocation-free workaround) ----------------
__device__ __align__(16) float g_featA[NN * HH];
__device__ __align__(16) float g_featB[NN * HH];
__device__ int   g_deg[NN];
__device__ float g_norm[NN];
__device__ float g_invdeg[NN];
__device__ float g_logdeg[NN];
__device__ int   g_scan[NN];
__device__ int   g_bsum[128];
__device__ int   g_rowstart[NN + 1];
__device__ int   g_rowcur[NN];
__device__ int   g_csr[EE];
__device__ int   g_pred[NN];
__device__ float g_f1[NN];
__device__ float g_f2[NN];
__device__ float g_partials[(NN / 32) * 4];
__device__ float g_ln[4];   // mean1, rstd1, mean2, rstd2
__device__ float g_clog[256];   // LUT: k * ln(k)
__device__ unsigned int g_ctr;

// ---------------- setup kernels ----------------
__global__ void k_zero() {
    int i = blockIdx.x * blockDim.x + threadIdx.x;
    if (i < NN) { g_deg[i] = 0; g_rowcur[i] = 0; }
    if (i == 0) g_ctr = 0u;
    if (i < 256) g_clog[i] = (i > 1) ? (float)i * logf((float)i) : 0.0f;
}

__global__ void k_deg(const int* __restrict__ dst) {
    int e = blockIdx.x * blockDim.x + threadIdx.x;
    if (e < EE) atomicAdd(&g_deg[dst[e]], 1);
}

__global__ void k_norm() {
    int i = blockIdx.x * blockDim.x + threadIdx.x;
    if (i < NN) {
        int d = g_deg[i];
        float dc = (d > 0) ? (float)d : 1.0f;
        g_norm[i] = rsqrtf(dc);
        g_invdeg[i] = 1.0f / dc;
        g_logdeg[i] = logf(dc);
    }
}

// inclusive scan within 1024-element blocks
__global__ void k_scan1() {
    __shared__ int sh[1024];
    int tid = threadIdx.x;
    int i = blockIdx.x * 1024 + tid;
    int v = (i < NN) ? g_deg[i] : 0;
    sh[tid] = v;
    __syncthreads();
    for (int off = 1; off < 1024; off <<= 1) {
        int t = (tid >= off) ? sh[tid - off] : 0;
        __syncthreads();
        sh[tid] += t;
        __syncthreads();
    }
    if (i < NN) g_scan[i] = sh[tid];
    if (tid == 1023) g_bsum[blockIdx.x] = sh[1023];
}

__global__ void k_scan2(int nb) {
    int run = 0;
    for (int b = 0; b < nb; b++) { int t = g_bsum[b]; g_bsum[b] = run; run += t; }
}

__global__ void k_scan3() {
    int i = blockIdx.x * blockDim.x + threadIdx.x;
    if (i < NN) g_rowstart[i] = g_scan[i] - g_deg[i] + g_bsum[i >> 10];
    if (i == 0) g_rowstart[NN] = EE;
}

__global__ void k_csrfill(const int* __restrict__ src, const int* __restrict__ dst) {
    int e = blockIdx.x * blockDim.x + threadIdx.x;
    if (e < EE) {
        int d = dst[e];
        int pos = g_rowstart[d] + atomicAdd(&g_rowcur[d], 1);
        g_csr[pos] = src[e];
    }
}

// feat buffer initialized to pre-scaled feat: Fs(0) = feat_in * norm
__global__ void k_init(const float* __restrict__ fin) {
    int i = blockIdx.x * blockDim.x + threadIdx.x;  // over NN*32 float4s
    if (i < NN * (HH / 4)) {
        int n = i >> 5;
        float nm = g_norm[n];
        float4 v = ((const float4*)fin)[i];
        v.x *= nm; v.y *= nm; v.z *= nm; v.w *= nm;
        ((float4*)g_featA)[i] = v;
    }
}

// ---------------- per-iteration kernels ----------------

// iteration 0: argmax over the input logits
__global__ void k_argmax0(const float* __restrict__ logits) {
    int n = (blockIdx.x * blockDim.x + threadIdx.x) >> 5;
    int lane = threadIdx.x & 31;
    if (n >= NN) return;
    const float* row = logits + (size_t)n * CC;
    float v0 = row[lane], v1 = row[lane + 32];
    float bv; int bc;
    if (v1 > v0) { bv = v1; bc = lane + 32; } else { bv = v0; bc = lane; }
    #pragma unroll
    for (int off = 16; off; off >>= 1) {
        float ov = __shfl_down_sync(0xffffffffu, bv, off);
        int   oc = __shfl_down_sync(0xffffffffu, bc, off);
        if (ov > bv || (ov == bv && oc < bc)) { bv = ov; bc = oc; }
    }
    if (lane == 0) g_pred[n] = bc;
}

// iterations 1..: fused GEMM (scaled feat @ w_y + b_y) + row argmax.
// (scalar FFMA, 8 nodes per warp register-blocked — proven round-2 version)
__global__ void __launch_bounds__(128) k_gemm_argmax(int sbuf, const float* __restrict__ w,
                                                     const float* __restrict__ b) {
    __shared__ float ws[HH * CC];                 // 32KB
    __shared__ float4 srow[4][8][HH / 4];         // 16KB
    const float* __restrict__ F = sbuf ? g_featB : g_featA;
    int tid = threadIdx.x;
    for (int i = tid; i < HH * CC / 4; i += 128)
        ((float4*)ws)[i] = ((const float4*)w)[i];
    __syncthreads();
    int wp = tid >> 5, lane = tid & 31;
    float2 bias = *(const float2*)&b[2 * lane];
    int base = blockIdx.x * 32 + wp * 8;

    float4 tmp[8];
    #pragma unroll
    for (int r = 0; r < 8; r++)
        tmp[r] = __ldg((const float4*)(F + (size_t)(base + r) * HH) + lane);
    #pragma unroll
    for (int r = 0; r < 8; r++)
        srow[wp][r][lane] = tmp[r];
    __syncwarp();

    float2 acc[8];
    #pragma unroll
    for (int r = 0; r < 8; r++) acc[r] = bias;

    const float2* ws2 = (const float2*)ws;
    #pragma unroll 4
    for (int k4 = 0; k4 < 32; k4++) {
        float2 w0 = ws2[(k4 * 4 + 0) * 32 + lane];
        float2 w1 = ws2[(k4 * 4 + 1) * 32 + lane];
        float2 w2 = ws2[(k4 * 4 + 2) * 32 + lane];
        float2 w3 = ws2[(k4 * 4 + 3) * 32 + lane];
        #pragma unroll
        for (int r = 0; r < 8; r++) {
            float4 f = srow[wp][r][k4];   // broadcast LDS.128
            acc[r].x = fmaf(f.x, w0.x, acc[r].x); acc[r].y = fmaf(f.x, w0.y, acc[r].y);
            acc[r].x = fmaf(f.y, w1.x, acc[r].x); acc[r].y = fmaf(f.y, w1.y, acc[r].y);
            acc[r].x = fmaf(f.z, w2.x, acc[r].x); acc[r].y = fmaf(f.z, w2.y, acc[r].y);
            acc[r].x = fmaf(f.w, w3.x, acc[r].x); acc[r].y = fmaf(f.w, w3.y, acc[r].y);
        }
    }

    #pragma unroll
    for (int r = 0; r < 8; r++) {
        float bv; int bc;
        if (acc[r].y > acc[r].x) { bv = acc[r].y; bc = 2 * lane + 1; }
        else                     { bv = acc[r].x; bc = 2 * lane; }
        #pragma unroll
        for (int off = 16; off; off >>= 1) {
            float ov = __shfl_down_sync(0xffffffffu, bv, off);
            int   oc = __shfl_down_sync(0xffffffffu, bc, off);
            if (ov > bv || (ov == bv && oc < bc)) { bv = ov; bc = oc; }
        }
        if (lane == 0) g_pred[base + r] = bc;
    }
}

// fused neighborhood stats: f1 (agreement) + f2 (entropy via integer LUT —
// NO logf on the hot path). match_any-aggregated smem histogram atomics.
// Entropy identity (clamp handled exactly):
//   f2 = -inv * sum_bins cnt*ln(cnt) + ln(deg_c) + nzero * KAPPA,  deg>0
//   (deg=0: all bins clamp -> 64*KAPPA; formula holds since ln(deg_c)=0)
// The LAST block also performs the LayerNorm finalize.
#define KAPPA 1.1512925e-4f   /* -1e-5*ln(1e-5) */
__global__ void k_stats() {
    __shared__ int hist[32][CC];
    __shared__ float4 red[32];
    __shared__ bool s_last;
    int tid = threadIdx.x, w = tid >> 5, lane = tid & 31;
    int n = blockIdx.x * 32 + w;
    hist[w][lane] = 0; hist[w][lane + 32] = 0;
    __syncwarp();
    int pd = g_pred[n];
    int rs = g_rowstart[n], re = g_rowstart[n + 1];
    int eq = 0;
    for (int base = rs; base < re; base += 32) {
        int idx = base + lane;
        int ps = (idx < re) ? __ldg(&g_pred[__ldg(&g_csr[idx])]) : -1;
        eq += (ps == pd);
        unsigned grp = __match_any_sync(0xffffffffu, ps);
        int leader = __ffs(grp) - 1;
        if (lane == leader && ps >= 0)
            atomicAdd(&hist[w][ps], __popc(grp));
    }
    __syncwarp();
    #pragma unroll
    for (int off = 16; off; off >>= 1) eq += __shfl_down_sync(0xffffffffu, eq, off);

    int c0 = hist[w][lane], c1 = hist[w][lane + 32];
    float S = __ldg(&g_clog[c0 < 255 ? c0 : 255]) + __ldg(&g_clog[c1 < 255 ? c1 : 255]);
    int nz = (c0 == 0) + (c1 == 0);
    #pragma unroll
    for (int off = 16; off; off >>= 1) {
        S  += __shfl_down_sync(0xffffffffu, S, off);
        nz += __shfl_down_sync(0xffffffffu, nz, off);
    }
    if (lane == 0) {
        float inv = g_invdeg[n];
        float f1 = (float)eq * inv;
        float f2 = fmaf(-inv, S, g_logdeg[n]) + (float)nz * KAPPA;
        g_f1[n] = f1; g_f2[n] = f2;
        red[w] = make_float4(f1, f1 * f1, f2, f2 * f2);
    }
    __syncthreads();
    if (tid < 4) {
        float s = 0.0f;
        #pragma unroll
        for (int ww = 0; ww < 32; ww++) s += ((const float*)&red[ww])[tid];
        g_partials[blockIdx.x * 4 + tid] = s;
    }

    // ---- last-block LayerNorm finalize ----
    __threadfence();
    if (tid == 0) {
        unsigned int prev = atomicInc(&g_ctr, gridDim.x - 1);  // self-wrapping
        s_last = (prev == gridDim.x - 1);
    }
    __syncthreads();
    if (!s_last) return;

    __shared__ float4 red4[1024];
    float s0 = 0, s1 = 0, s2 = 0, s3 = 0;
    for (int bk = tid; bk < NN / 32; bk += 1024) {
        s0 += g_partials[4 * bk + 0];
        s1 += g_partials[4 * bk + 1];
        s2 += g_partials[4 * bk + 2];
        s3 += g_partials[4 * bk + 3];
    }
    red4[tid] = make_float4(s0, s1, s2, s3);
    __syncthreads();
    for (int off = 512; off; off >>= 1) {
        if (tid < off) {
            red4[tid].x += red4[tid + off].x;
            red4[tid].y += red4[tid + off].y;
            red4[tid].z += red4[tid + off].z;
            red4[tid].w += red4[tid + off].w;
        }
        __syncthreads();
    }
    if (tid == 0) {
        const float invN = 1.0f / (float)NN;
        float m1 = red4[0].x * invN;
        float v1 = red4[0].y * invN - m1 * m1;
        float m2 = red4[0].z * invN;
        float v2 = red4[0].w * invN - m2 * m2;
        g_ln[0] = m1; g_ln[1] = rsqrtf(v1 + 1e-5f);
        g_ln[2] = m2; g_ln[3] = rsqrtf(v2 + 1e-5f);
    }
}

// fused SpMM gather + gate + combine + (folded) next-iteration scale (fp32).
__global__ void k_spmm(int sbuf, float* __restrict__ dout, int last,
                       const float* __restrict__ tau1, const float* __restrict__ tau2) {
    int n = (blockIdx.x * blockDim.x + threadIdx.x) >> 5;
    int lane = threadIdx.x & 31;
    if (n >= NN) return;
    const float* __restrict__ Fs = sbuf ? g_featB : g_featA;
    float* __restrict__ Fd = last ? dout : (sbuf ? g_featA : g_featB);

    int rs = g_rowstart[n], re = g_rowstart[n + 1];
    float4 acc = make_float4(0.f, 0.f, 0.f, 0.f);
    int idx = rs;
    for (; idx + 4 <= re; idx += 4) {
        int s0 = g_csr[idx], s1 = g_csr[idx + 1], s2 = g_csr[idx + 2], s3 = g_csr[idx + 3];
        float4 v0 = __ldg((const float4*)(Fs + (size_t)s0 * HH) + lane);
        float4 v1 = __ldg((const float4*)(Fs + (size_t)s1 * HH) + lane);
        float4 v2 = __ldg((const float4*)(Fs + (size_t)s2 * HH) + lane);
        float4 v3 = __ldg((const float4*)(Fs + (size_t)s3 * HH) + lane);
        acc.x += (v0.x + v1.x) + (v2.x + v3.x);
        acc.y += (v0.y + v1.y) + (v2.y + v3.y);
        acc.z += (v0.z + v1.z) + (v2.z + v3.z);
        acc.w += (v0.w + v1.w) + (v2.w + v3.w);
    }
    for (; idx < re; idx++) {
        int s = g_csr[idx];
        float4 v = __ldg((const float4*)(Fs + (size_t)s * HH) + lane);
        acc.x += v.x; acc.y += v.y; acc.z += v.z; acc.w += v.w;
    }

    float m1 = g_ln[0], r1 = g_ln[1], m2 = g_ln[2], r2 = g_ln[3];
    float z1 = 1.0f / (1.0f + expf((g_f1[n] - m1) * r1 - tau1[0]));
    float z2 = 1.0f / (1.0f + expf((g_f2[n] - m2) * r2 - tau2[0]));
    float z = z1 * z2;
    float nm = g_norm[n];
    float s_agg = last ? (z * nm) : (z * nm * nm);
    float s_own = last ? 1.0f : nm;

    float4 own = ((const float4*)(Fs + (size_t)n * HH))[lane];
    float4 o;
    o.x = s_agg * acc.x + s_own * own.x;
    o.y = s_agg * acc.y + s_own * own.y;
    o.z = s_agg * acc.z + s_own * own.z;
    o.w = s_agg * acc.w + s_own * own.w;
    __stcs((float4*)(Fd + (size_t)n * HH) + lane, o);
}

// ---------------- host launcher ----------------
extern "C" void kernel_launch(void* const* d_in, const int* in_sizes, int n_in,
                              void* d_out, int out_size) {
    const float* feat   = (const float*)d_in[0];
    const float* logits = (const float*)d_in[1];
    const float* w_y    = (const float*)d_in[2];
    const float* b_y    = (const float*)d_in[3];
    const float* tau1   = (const float*)d_in[4];
    const float* tau2   = (const float*)d_in[5];
    const int*   src    = (const int*)d_in[6];
    const int*   dst    = (const int*)d_in[7];
    float* out = (float*)d_out;
    (void)in_sizes; (void)n_in; (void)out_size;

    const int NB1 = (NN + 1023) / 1024;  // 98

    k_zero<<<(NN + 255) / 256, 256>>>();
    k_deg<<<(EE + 255) / 256, 256>>>(dst);
    k_norm<<<(NN + 255) / 256, 256>>>();
    k_scan1<<<NB1, 1024>>>();
    k_scan2<<<1, 1>>>(NB1);
    k_scan3<<<(NN + 255) / 256, 256>>>();
    k_csrfill<<<(EE + 255) / 256, 256>>>(src, dst);
    k_init<<<(NN * (HH / 4) + 255) / 256, 256>>>(feat);

    const int warp_blocks = (NN * 32 + 255) / 256;   // warp-per-node grids
    for (int i = 0; i < KK; i++) {
        int sbuf = i & 1;  // 0 -> g_featA source, 1 -> g_featB source
        if (i == 0) {
            k_argmax0<<<warp_blocks, 256>>>(logits);
        } else {
            k_gemm_argmax<<<NN / 32, 128>>>(sbuf, w_y, b_y);
        }
        k_stats<<<NN / 32, 1024>>>();
        k_spmm<<<warp_blocks, 256>>>(sbuf, out, (i == KK - 1) ? 1 : 0, tau1, tau2);
    }
}

// round 7
// speedup vs baseline: 1.1377x; 1.1377x over previous
#include <cuda_runtime.h>
#include <math.h>

#define NN 100000
#define EE 1600000
#define HH 128
#define CC 64
#define KK 10

typedef unsigned long long u64;

// ---------------- device scratch (allocation-free workaround) ----------------
__device__ __align__(16) float g_featA[NN * HH];
__device__ __align__(16) float g_featB[NN * HH];
__device__ int   g_deg[NN];
__device__ float g_norm[NN];
__device__ float g_invdeg[NN];
__device__ int   g_scan[NN];
__device__ int   g_bsum[128];
__device__ int   g_rowstart[NN + 1];
__device__ int   g_rowcur[NN];
__device__ int   g_csr[EE];
__device__ int   g_pred[NN];
__device__ float g_f1[NN];
__device__ float g_f2[NN];
__device__ float g_partials[(NN / 32) * 4];
__device__ float g_ln[4];   // mean1, rstd1, mean2, rstd2

// ---------------- packed fp32x2 helpers ----------------
__device__ __forceinline__ u64 ffma2(u64 a, u64 b, u64 c) {
    u64 d;
    asm("fma.rn.f32x2 %0, %1, %2, %3;" : "=l"(d) : "l"(a), "l"(b), "l"(c));
    return d;
}
__device__ __forceinline__ u64 pk(float x, float y) {
    u64 d;
    asm("mov.b64 %0, {%1, %2};" : "=l"(d) : "f"(x), "f"(y));
    return d;
}
__device__ __forceinline__ float2 upk(u64 v) {
    float2 r;
    asm("mov.b64 {%0, %1}, %2;" : "=f"(r.x), "=f"(r.y) : "l"(v));
    return r;
}

// ---------------- setup kernels ----------------
__global__ void k_zero() {
    int i = blockIdx.x * blockDim.x + threadIdx.x;
    if (i < NN) { g_deg[i] = 0; g_rowcur[i] = 0; }
}

__global__ void k_deg(const int* __restrict__ dst) {
    int e = blockIdx.x * blockDim.x + threadIdx.x;
    if (e < EE) atomicAdd(&g_deg[dst[e]], 1);
}

__global__ void k_norm() {
    int i = blockIdx.x * blockDim.x + threadIdx.x;
    if (i < NN) {
        int d = g_deg[i];
        float dc = (d > 0) ? (float)d : 1.0f;
        g_norm[i] = rsqrtf(dc);
        g_invdeg[i] = 1.0f / dc;
    }
}

// inclusive scan within 1024-element blocks
__global__ void k_scan1() {
    __shared__ int sh[1024];
    int tid = threadIdx.x;
    int i = blockIdx.x * 1024 + tid;
    int v = (i < NN) ? g_deg[i] : 0;
    sh[tid] = v;
    __syncthreads();
    for (int off = 1; off < 1024; off <<= 1) {
        int t = (tid >= off) ? sh[tid - off] : 0;
        __syncthreads();
        sh[tid] += t;
        __syncthreads();
    }
    if (i < NN) g_scan[i] = sh[tid];
    if (tid == 1023) g_bsum[blockIdx.x] = sh[1023];
}

__global__ void k_scan2(int nb) {
    int run = 0;
    for (int b = 0; b < nb; b++) { int t = g_bsum[b]; g_bsum[b] = run; run += t; }
}

__global__ void k_scan3() {
    int i = blockIdx.x * blockDim.x + threadIdx.x;
    if (i < NN) g_rowstart[i] = g_scan[i] - g_deg[i] + g_bsum[i >> 10];
    if (i == 0) g_rowstart[NN] = EE;
}

__global__ void k_csrfill(const int* __restrict__ src, const int* __restrict__ dst) {
    int e = blockIdx.x * blockDim.x + threadIdx.x;
    if (e < EE) {
        int d = dst[e];
        int pos = g_rowstart[d] + atomicAdd(&g_rowcur[d], 1);
        g_csr[pos] = src[e];
    }
}

// feat buffer initialized to pre-scaled feat: Fs(0) = feat_in * norm
__global__ void k_init(const float* __restrict__ fin) {
    int i = blockIdx.x * blockDim.x + threadIdx.x;  // over NN*32 float4s
    if (i < NN * (HH / 4)) {
        int n = i >> 5;
        float nm = g_norm[n];
        float4 v = ((const float4*)fin)[i];
        v.x *= nm; v.y *= nm; v.z *= nm; v.w *= nm;
        ((float4*)g_featA)[i] = v;
    }
}

// ---------------- per-iteration kernels ----------------

// iteration 0: argmax over the input logits
__global__ void k_argmax0(const float* __restrict__ logits) {
    int n = (blockIdx.x * blockDim.x + threadIdx.x) >> 5;
    int lane = threadIdx.x & 31;
    if (n >= NN) return;
    const float* row = logits + (size_t)n * CC;
    float v0 = row[lane], v1 = row[lane + 32];
    float bv; int bc;
    if (v1 > v0) { bv = v1; bc = lane + 32; } else { bv = v0; bc = lane; }
    #pragma unroll
    for (int off = 16; off; off >>= 1) {
        float ov = __shfl_down_sync(0xffffffffu, bv, off);
        int   oc = __shfl_down_sync(0xffffffffu, bc, off);
        if (ov > bv || (ov == bv && oc < bc)) { bv = ov; bc = oc; }
    }
    if (lane == 0) g_pred[n] = bc;
}

// iterations 1..: fused GEMM (scaled feat @ w_y + b_y) + row argmax.
// K-packed FFMA2: each u64 accumulator holds (even-k, odd-k) partial sums.
// f pairs come from LDS.128 of the staged row (float4 = two natural u64s);
// w pairs from transposed ws_t[c][k] with pitch 130 (conflict-free LDS.64).
// Lane owns classes (lane, lane+32) for 8 nodes. NN % 32 == 0.
#define WTP 130
__global__ void __launch_bounds__(128) k_gemm_argmax(int sbuf, const float* __restrict__ w,
                                                     const float* __restrict__ b) {
    __shared__ __align__(8) float ws_t[CC][WTP];        // ~33 KB transposed [c][k]
    __shared__ __align__(16) float4 srow[4][8][HH / 4]; // 16 KB
    const float* __restrict__ F = sbuf ? g_featB : g_featA;
    int tid = threadIdx.x;

    // transpose w (k-major [HH][CC]) into ws_t[c][k]
    for (int i = tid; i < HH * CC / 4; i += 128) {
        float4 v = ((const float4*)w)[i];
        int k = i >> 4;            // 16 float4 per k-row
        int c = (i & 15) * 4;
        ws_t[c + 0][k] = v.x; ws_t[c + 1][k] = v.y;
        ws_t[c + 2][k] = v.z; ws_t[c + 3][k] = v.w;
    }
    __syncthreads();

    int wp = tid >> 5, lane = tid & 31;
    int base = blockIdx.x * 32 + wp * 8;

    // stage 8 rows
    float4 tmp[8];
    #pragma unroll
    for (int r = 0; r < 8; r++)
        tmp[r] = __ldg((const float4*)(F + (size_t)(base + r) * HH) + lane);
    #pragma unroll
    for (int r = 0; r < 8; r++)
        srow[wp][r][lane] = tmp[r];
    __syncwarp();

    u64 acc0[8], acc1[8];
    #pragma unroll
    for (int r = 0; r < 8; r++) { acc0[r] = 0ull; acc1[r] = 0ull; }

    const u64* w0p = (const u64*)&ws_t[lane][0];
    const u64* w1p = (const u64*)&ws_t[lane + 32][0];
    const float4* fr = &srow[wp][0][0];   // rows are HH/4 float4s apart

    #pragma unroll 4
    for (int k4 = 0; k4 < HH / 4; k4++) {       // each k4 covers k-pairs 2k4, 2k4+1
        u64 wa0 = w0p[2 * k4], wa1 = w0p[2 * k4 + 1];
        u64 wb0 = w1p[2 * k4], wb1 = w1p[2 * k4 + 1];
        #pragma unroll
        for (int r = 0; r < 8; r++) {
            float4 f = fr[r * (HH / 4) + k4];   // broadcast LDS.128
            u64 fp0 = pk(f.x, f.y);
            u64 fp1 = pk(f.z, f.w);
            acc0[r] = ffma2(fp0, wa0, acc0[r]);
            acc0[r] = ffma2(fp1, wa1, acc0[r]);
            acc1[r] = ffma2(fp0, wb0, acc1[r]);
            acc1[r] = ffma2(fp1, wb1, acc1[r]);
        }
    }

    float bias0 = b[lane], bias1 = b[lane + 32];
    #pragma unroll
    for (int r = 0; r < 8; r++) {
        float2 a0 = upk(acc0[r]);
        float2 a1 = upk(acc1[r]);
        float l0 = (a0.x + a0.y) + bias0;
        float l1 = (a1.x + a1.y) + bias1;
        float bv; int bc;
        if (l1 > l0) { bv = l1; bc = lane + 32; } else { bv = l0; bc = lane; }
        #pragma unroll
        for (int off = 16; off; off >>= 1) {
            float ov = __shfl_down_sync(0xffffffffu, bv, off);
            int   oc = __shfl_down_sync(0xffffffffu, bc, off);
            if (ov > bv || (ov == bv && oc < bc)) { bv = ov; bc = oc; }
        }
        if (lane == 0) g_pred[base + r] = bc;
    }
}

// fused neighborhood stats: f1 (agreement) + f2 (entropy of class histogram),
// warp per node with a 64-bin smem histogram; emits per-block LN partials.
// (round-2 proven version: plain atomics + logf, separate k_ln finalize)
__global__ void k_stats() {
    __shared__ int hist[32][CC];
    __shared__ float4 red[32];
    int tid = threadIdx.x, w = tid >> 5, lane = tid & 31;
    int n = blockIdx.x * 32 + w;
    hist[w][lane] = 0; hist[w][lane + 32] = 0;
    __syncwarp();
    int pd = g_pred[n];
    int rs = g_rowstart[n], re = g_rowstart[n + 1];
    int eq = 0;
    for (int idx = rs + lane; idx < re; idx += 32) {
        int ps = g_pred[g_csr[idx]];
        eq += (ps == pd);
        atomicAdd(&hist[w][ps], 1);
    }
    __syncwarp();
    #pragma unroll
    for (int off = 16; off; off >>= 1) eq += __shfl_down_sync(0xffffffffu, eq, off);
    float inv = g_invdeg[n];
    float p0 = fmaxf((float)hist[w][lane] * inv, 1e-5f);
    float p1 = fmaxf((float)hist[w][lane + 32] * inv, 1e-5f);
    float ent = -(p0 * logf(p0) + p1 * logf(p1));
    #pragma unroll
    for (int off = 16; off; off >>= 1) ent += __shfl_down_sync(0xffffffffu, ent, off);
    if (lane == 0) {
        float f1 = (float)eq * inv;
        g_f1[n] = f1; g_f2[n] = ent;
        red[w] = make_float4(f1, f1 * f1, ent, ent * ent);
    }
    __syncthreads();
    if (tid < 4) {
        float s = 0.0f;
        #pragma unroll
        for (int ww = 0; ww < 32; ww++) s += ((const float*)&red[ww])[tid];
        g_partials[blockIdx.x * 4 + tid] = s;
    }
}

// single-block deterministic finalize of LayerNorm stats over N
__global__ void k_ln() {
    __shared__ float4 red4[1024];
    int tid = threadIdx.x;
    float s0 = 0, s1 = 0, s2 = 0, s3 = 0;
    for (int b = tid; b < NN / 32; b += 1024) {
        s0 += g_partials[4 * b + 0];
        s1 += g_partials[4 * b + 1];
        s2 += g_partials[4 * b + 2];
        s3 += g_partials[4 * b + 3];
    }
    red4[tid] = make_float4(s0, s1, s2, s3);
    __syncthreads();
    for (int off = 512; off; off >>= 1) {
        if (tid < off) {
            red4[tid].x += red4[tid + off].x;
            red4[tid].y += red4[tid + off].y;
            red4[tid].z += red4[tid + off].z;
            red4[tid].w += red4[tid + off].w;
        }
        __syncthreads();
    }
    if (tid == 0) {
        const float invN = 1.0f / (float)NN;
        float m1 = red4[0].x * invN;
        float v1 = red4[0].y * invN - m1 * m1;
        float m2 = red4[0].z * invN;
        float v2 = red4[0].w * invN - m2 * m2;
        g_ln[0] = m1; g_ln[1] = rsqrtf(v1 + 1e-5f);
        g_ln[2] = m2; g_ln[3] = rsqrtf(v2 + 1e-5f);
    }
}

// fused SpMM gather + gate + combine + (folded) next-iteration scale (fp32).
__global__ void k_spmm(int sbuf, float* __restrict__ dout, int last,
                       const float* __restrict__ tau1, const float* __restrict__ tau2) {
    int n = (blockIdx.x * blockDim.x + threadIdx.x) >> 5;
    int lane = threadIdx.x & 31;
    if (n >= NN) return;
    const float* __restrict__ Fs = sbuf ? g_featB : g_featA;
    float* __restrict__ Fd = last ? dout : (sbuf ? g_featA : g_featB);

    int rs = g_rowstart[n], re = g_rowstart[n + 1];
    float4 acc = make_float4(0.f, 0.f, 0.f, 0.f);
    int idx = rs;
    for (; idx + 4 <= re; idx += 4) {
        int s0 = g_csr[idx], s1 = g_csr[idx + 1], s2 = g_csr[idx + 2], s3 = g_csr[idx + 3];
        float4 v0 = __ldg((const float4*)(Fs + (size_t)s0 * HH) + lane);
        float4 v1 = __ldg((const float4*)(Fs + (size_t)s1 * HH) + lane);
        float4 v2 = __ldg((const float4*)(Fs + (size_t)s2 * HH) + lane);
        float4 v3 = __ldg((const float4*)(Fs + (size_t)s3 * HH) + lane);
        acc.x += (v0.x + v1.x) + (v2.x + v3.x);
        acc.y += (v0.y + v1.y) + (v2.y + v3.y);
        acc.z += (v0.z + v1.z) + (v2.z + v3.z);
        acc.w += (v0.w + v1.w) + (v2.w + v3.w);
    }
    for (; idx < re; idx++) {
        int s = g_csr[idx];
        float4 v = __ldg((const float4*)(Fs + (size_t)s * HH) + lane);
        acc.x += v.x; acc.y += v.y; acc.z += v.z; acc.w += v.w;
    }

    float m1 = g_ln[0], r1 = g_ln[1], m2 = g_ln[2], r2 = g_ln[3];
    float z1 = 1.0f / (1.0f + expf((g_f1[n] - m1) * r1 - tau1[0]));
    float z2 = 1.0f / (1.0f + expf((g_f2[n] - m2) * r2 - tau2[0]));
    float z = z1 * z2;
    float nm = g_norm[n];
    float s_agg = last ? (z * nm) : (z * nm * nm);
    float s_own = last ? 1.0f : nm;

    float4 own = ((const float4*)(Fs + (size_t)n * HH))[lane];
    float4 o;
    o.x = s_agg * acc.x + s_own * own.x;
    o.y = s_agg * acc.y + s_own * own.y;
    o.z = s_agg * acc.z + s_own * own.z;
    o.w = s_agg * acc.w + s_own * own.w;
    __stcs((float4*)(Fd + (size_t)n * HH) + lane, o);
}

// ---------------- host launcher ----------------
extern "C" void kernel_launch(void* const* d_in, const int* in_sizes, int n_in,
                              void* d_out, int out_size) {
    const float* feat   = (const float*)d_in[0];
    const float* logits = (const float*)d_in[1];
    const float* w_y    = (const float*)d_in[2];
    const float* b_y    = (const float*)d_in[3];
    const float* tau1   = (const float*)d_in[4];
    const float* tau2   = (const float*)d_in[5];
    const int*   src    = (const int*)d_in[6];
    const int*   dst    = (const int*)d_in[7];
    float* out = (float*)d_out;
    (void)in_sizes; (void)n_in; (void)out_size;

    const int NB1 = (NN + 1023) / 1024;  // 98

    k_zero<<<(NN + 255) / 256, 256>>>();
    k_deg<<<(EE + 255) / 256, 256>>>(dst);
    k_norm<<<(NN + 255) / 256, 256>>>();
    k_scan1<<<NB1, 1024>>>();
    k_scan2<<<1, 1>>>(NB1);
    k_scan3<<<(NN + 255) / 256, 256>>>();
    k_csrfill<<<(EE + 255) / 256, 256>>>(src, dst);
    k_init<<<(NN * (HH / 4) + 255) / 256, 256>>>(feat);

    const int warp_blocks = (NN * 32 + 255) / 256;   // warp-per-node grids
    for (int i = 0; i < KK; i++) {
        int sbuf = i & 1;  // 0 -> g_featA source, 1 -> g_featB source
        if (i == 0) {
            k_argmax0<<<warp_blocks, 256>>>(logits);
        } else {
            k_gemm_argmax<<<NN / 32, 128>>>(sbuf, w_y, b_y);
        }
        k_stats<<<NN / 32, 1024>>>();
        k_ln<<<1, 1024>>>();
        k_spmm<<<warp_blocks, 256>>>(sbuf, out, (i == KK - 1) ? 1 : 0, tau1, tau2);
    }
}